// round 2
// baseline (speedup 1.0000x reference)
#include <cuda_runtime.h>

// LengthRegulator: the conv/LN/linear "predictor" in the reference is dead code
// (its result is overridden by target_durations). Real work:
//   cum = cumsum(durations) per batch; out[b,f,:] = f < cum[T-1] ? x[b, ub(cum,f), :] : 0
// plus durations echoed as the second output.

#define BB 8
#define TT 1024
#define DD 1024
#define FF 8192   // MAX_FRAMES = T * DMAX

// token index per (b, frame); -1 means invalid (zero-fill). 256 KB scratch.
__device__ int g_tok[BB * FF];

// One block per batch row: scan durations, binary-search all 8192 frames,
// and emit the durations tail of the output.
__global__ void lr_prep_kernel(const int* __restrict__ dur,
                               float* __restrict__ out_tail,
                               int write_tail) {
    const int b = blockIdx.x;
    const int t = threadIdx.x;

    __shared__ int s[TT];
    const int d = dur[b * TT + t];
    s[t] = d;
    __syncthreads();

    // Hillis–Steele inclusive scan over 1024 elements (10 steps).
    #pragma unroll
    for (int off = 1; off < TT; off <<= 1) {
        const int v = (t >= off) ? s[t - off] : 0;
        __syncthreads();
        s[t] += v;
        __syncthreads();
    }
    const int total = s[TT - 1];

    // Each thread resolves 8 frames: upper_bound(cum, f) -> first i with cum[i] > f.
    #pragma unroll
    for (int k = 0; k < FF / TT; ++k) {
        const int f = t + k * TT;
        int tok;
        if (f >= total) {
            tok = -1;
        } else {
            // Search to convergence: interval [0,1024] holds 1025 candidates, so
            // a fixed 10 iterations can leave hi-lo==1 (prev round's off-by-one).
            int lo = 0, hi = TT;
            while (lo < hi) {
                const int mid = (lo + hi) >> 1;
                if (s[mid] > f) hi = mid; else lo = mid + 1;
            }
            tok = lo;   // f < total == s[TT-1] guarantees lo <= TT-1 (in bounds)
        }
        g_tok[b * FF + f] = tok;
    }

    if (write_tail) {
        out_tail[b * TT + t] = (float)d;   // durations, numerically cast to output dtype
    }
}

// One block per (b, frame): copy one 4 KB row of x (or zero-fill) with float4 stores.
__global__ void lr_expand_kernel(const float* __restrict__ x,
                                 float* __restrict__ out) {
    const int idx = blockIdx.x;           // b * FF + f
    const int b   = idx >> 13;            // FF = 8192
    const int tok = g_tok[idx];           // uniform across block (broadcast load)
    const int c   = threadIdx.x;          // 0..255, one float4 each -> D=1024 floats

    float4* dst = reinterpret_cast<float4*>(out) + (size_t)idx * (DD / 4);
    if (tok >= 0) {
        const float4* src = reinterpret_cast<const float4*>(x)
                          + ((size_t)b * TT + tok) * (DD / 4);
        dst[c] = src[c];
    } else {
        dst[c] = make_float4(0.f, 0.f, 0.f, 0.f);
    }
}

extern "C" void kernel_launch(void* const* d_in, const int* in_sizes, int n_in,
                              void* d_out, int out_size) {
    const float* x   = (const float*)d_in[0];   // [B, T, D] f32
    const int*   dur = (const int*)d_in[1];     // [B, T] i32
    float* out = (float*)d_out;

    const long long padded_elems = (long long)BB * FF * DD;   // 67,108,864
    const int write_tail = (out_size >= padded_elems + BB * TT) ? 1 : 0;

    lr_prep_kernel<<<BB, TT>>>(dur, out + padded_elems, write_tail);
    lr_expand_kernel<<<BB * FF, DD / 4>>>(x, out);
}

// round 3
// speedup vs baseline: 1.4066x; 1.4066x over previous
#include <cuda_runtime.h>

// LengthRegulator: predictor in the reference is dead code (overridden by
// target_durations). Real work: per-batch cumsum + upper_bound gather-expand.

#define BB 8
#define TT 1024
#define DD 1024
#define FF 8192   // MAX_FRAMES = T * DMAX
#define NF 8      // frames per expand block (MLP per thread)

// token index per (b, frame); -1 means invalid (zero-fill). 256 KB scratch.
__device__ int g_tok[BB * FF];

// One block per batch row: scan durations, binary-search all 8192 frames,
// and emit the durations tail of the output.
__global__ void lr_prep_kernel(const int* __restrict__ dur,
                               float* __restrict__ out_tail,
                               int write_tail) {
    const int b = blockIdx.x;
    const int t = threadIdx.x;

    __shared__ int s[TT];
    const int d = dur[b * TT + t];
    s[t] = d;
    __syncthreads();

    // Hillis–Steele inclusive scan over 1024 elements (10 steps).
    #pragma unroll
    for (int off = 1; off < TT; off <<= 1) {
        const int v = (t >= off) ? s[t - off] : 0;
        __syncthreads();
        s[t] += v;
        __syncthreads();
    }
    const int total = s[TT - 1];

    // Each thread resolves 8 frames: upper_bound(cum, f) -> first i with cum[i] > f.
    #pragma unroll
    for (int k = 0; k < FF / TT; ++k) {
        const int f = t + k * TT;
        int tok;
        if (f >= total) {
            tok = -1;
        } else {
            int lo = 0, hi = TT;
            while (lo < hi) {              // run to convergence (1025 candidates)
                const int mid = (lo + hi) >> 1;
                if (s[mid] > f) hi = mid; else lo = mid + 1;
            }
            tok = lo;                      // f < total guarantees lo <= TT-1
        }
        g_tok[b * FF + f] = tok;
    }

    if (write_tail) {
        out_tail[b * TT + t] = (float)d;   // durations, numeric cast to f32 output
    }
}

// One block per group of NF consecutive frames of one batch row.
// Each thread: NF independent tok loads -> NF independent LDG.128 (MLP=NF)
// -> NF streaming STG.128. Duplicate toks within the group hit L1.
__global__ void __launch_bounds__(DD / 4)
lr_expand_kernel(const float* __restrict__ x, float* __restrict__ out) {
    const int base = blockIdx.x * NF;     // b * FF + f of first frame in group
    const int b    = base >> 13;          // FF = 8192, NF divides FF
    const int c    = threadIdx.x;         // 0..255, one float4 column each

    int tok[NF];
    #pragma unroll
    for (int i = 0; i < NF; ++i)
        tok[i] = g_tok[base + i];         // independent, overlapped, L2-resident

    const float4* xb = reinterpret_cast<const float4*>(x)
                     + (size_t)b * TT * (DD / 4);
    float4 v[NF];
    #pragma unroll
    for (int i = 0; i < NF; ++i) {
        if (tok[i] >= 0)
            v[i] = __ldg(&xb[(size_t)tok[i] * (DD / 4) + c]);
        else
            v[i] = make_float4(0.f, 0.f, 0.f, 0.f);
    }

    float4* dst = reinterpret_cast<float4*>(out) + (size_t)base * (DD / 4) + c;
    #pragma unroll
    for (int i = 0; i < NF; ++i)
        __stcs(&dst[(size_t)i * (DD / 4)], v[i]);   // streaming: don't pollute L2
}

extern "C" void kernel_launch(void* const* d_in, const int* in_sizes, int n_in,
                              void* d_out, int out_size) {
    const float* x   = (const float*)d_in[0];   // [B, T, D] f32
    const int*   dur = (const int*)d_in[1];     // [B, T] i32
    float* out = (float*)d_out;

    const long long padded_elems = (long long)BB * FF * DD;   // 67,108,864
    const int write_tail = (out_size >= padded_elems + BB * TT) ? 1 : 0;

    lr_prep_kernel<<<BB, TT>>>(dur, out + padded_elems, write_tail);
    lr_expand_kernel<<<(BB * FF) / NF, DD / 4>>>(x, out);
}